// round 3
// baseline (speedup 1.0000x reference)
#include <cuda_runtime.h>

// newPad2d: replicate (edge) pad, width 2 on H and W.
// in:  (32, 256, 56, 56) fp32 -> 8192 planes of 56x56
// out: (32, 256, 60, 60) fp32 -> 8192 planes of 60x60
//
// Output row = 60 floats = 15 aligned float4 stores.
// Because every output vec starts at w0 = 4k, the source window [w0-2, w0+2)
// is 8-byte aligned: each vec needs exactly TWO aligned LDG.64 (float2)
// loads + 2 selects, instead of 4 scalar gathers. ILP=8 output vecs per
// thread front-batches 16 independent LDG.64s to hide DRAM latency.
// nvec = 7,372,800 = 3600 * 2048 exactly -> no tail.

#define IN_H   56
#define IN_W   56
#define PAD    2
#define PLANE_IN      (IN_H * IN_W)          // 3136
#define VEC_PER_ROW   15                     // 60/4
#define VEC_PER_PLANE (60 * VEC_PER_ROW)     // 900
#define ILP 8
#define THREADS 256
#define CHUNK (THREADS * ILP)                // 2048

__global__ __launch_bounds__(THREADS)
void pad2d_edge_f2(const float* __restrict__ x,
                   float4* __restrict__ out)
{
    const int base = blockIdx.x * CHUNK + threadIdx.x;

    float2 a[ILP], b[ILP];
    int    w0[ILP];

#pragma unroll
    for (int k = 0; k < ILP; k++) {
        int idx   = base + k * THREADS;
        int plane = idx / VEC_PER_PLANE;
        int rem   = idx - plane * VEC_PER_PLANE;
        int h     = rem / VEC_PER_ROW;
        int w     = (rem - h * VEC_PER_ROW) * 4;
        w0[k]     = w;
        int hin   = min(max(h - PAD, 0), IN_H - 1);
        int off   = plane * PLANE_IN + hin * IN_W;   // fits in 32-bit (25.7M)

        // both 8-byte aligned
        a[k] = *(const float2*)(x + off + max(w - 2, 0));
        b[k] = *(const float2*)(x + off + min(w, IN_W - 2));
    }

#pragma unroll
    for (int k = 0; k < ILP; k++) {
        int w = w0[k];
        float4 v;
        v.x = a[k].x;
        v.y = (w == 0)        ? a[k].x : a[k].y;
        v.z = (w == IN_W)     ? b[k].y : b[k].x;   // w==56 -> right edge
        v.w = b[k].y;
        out[base + k * THREADS] = v;
    }
}

extern "C" void kernel_launch(void* const* d_in, const int* in_sizes, int n_in,
                              void* d_out, int out_size)
{
    const float* x = (const float*)d_in[0];
    float4* out = (float4*)d_out;

    int nvec = out_size / 4;        // 7,372,800
    int blocks = nvec / CHUNK;      // 3600 exactly
    pad2d_edge_f2<<<blocks, THREADS>>>(x, out);
}

// round 4
// speedup vs baseline: 1.0206x; 1.0206x over previous
#include <cuda_runtime.h>

// newPad2d: replicate (edge) pad, width 2 on H and W.
// in:  (32, 256, 56, 56) fp32 -> 8192 planes of 56x56
// out: (32, 256, 60, 60) fp32 -> 8192 planes of 60x60
//
// R2 occupancy (ILP=4, low regs) + R3 float2 loads:
// every output vec starts at w0 = 4k, so the source window [w0-2, w0+2) is
// 8-byte aligned -> exactly 2 aligned LDG.64 per output float4, plus 2 SELs.
// ILP=4 keeps regs ~32-36 so occupancy stays high, while the 8 independent
// LDG.64s per thread are front-batched for MLP.
// nvec = 7,372,800 = 7200 * 1024 exactly -> no tail.

#define IN_H   56
#define IN_W   56
#define PAD    2
#define PLANE_IN      (IN_H * IN_W)          // 3136
#define VEC_PER_ROW   15                     // 60/4
#define VEC_PER_PLANE (60 * VEC_PER_ROW)     // 900
#define ILP 4
#define THREADS 256
#define CHUNK (THREADS * ILP)                // 1024

__global__ __launch_bounds__(THREADS)
void pad2d_edge_f2_ilp4(const float* __restrict__ x,
                        float4* __restrict__ out)
{
    const int base = blockIdx.x * CHUNK + threadIdx.x;

    float2 a[ILP], b[ILP];
    int    w0[ILP];

#pragma unroll
    for (int k = 0; k < ILP; k++) {
        int idx   = base + k * THREADS;
        int plane = idx / VEC_PER_PLANE;
        int rem   = idx - plane * VEC_PER_PLANE;
        int h     = rem / VEC_PER_ROW;
        int w     = (rem - h * VEC_PER_ROW) * 4;
        w0[k]     = w;
        int hin   = min(max(h - PAD, 0), IN_H - 1);
        int off   = plane * PLANE_IN + hin * IN_W;   // max ~25.7M, fits 32-bit

        // both addresses 8-byte aligned
        a[k] = *(const float2*)(x + off + max(w - 2, 0));
        b[k] = *(const float2*)(x + off + min(w, IN_W - 2));
    }

#pragma unroll
    for (int k = 0; k < ILP; k++) {
        int w = w0[k];
        float4 v;
        v.x = a[k].x;
        v.y = (w == 0)    ? a[k].x : a[k].y;   // left edge vec replicates col 0
        v.z = (w == IN_W) ? b[k].y : b[k].x;   // right edge vec replicates col 55
        v.w = b[k].y;
        out[base + k * THREADS] = v;
    }
}

extern "C" void kernel_launch(void* const* d_in, const int* in_sizes, int n_in,
                              void* d_out, int out_size)
{
    const float* x = (const float*)d_in[0];
    float4* out = (float4*)d_out;

    int nvec = out_size / 4;        // 7,372,800
    int blocks = nvec / CHUNK;      // 7200 exactly
    pad2d_edge_f2_ilp4<<<blocks, THREADS>>>(x, out);
}

// round 6
// speedup vs baseline: 1.0214x; 1.0008x over previous
#include <cuda_runtime.h>

// newPad2d: replicate (edge) pad, width 2 on H and W.
// in:  (32, 256, 56, 56) fp32 = 98 MB  -> 8192 planes of 56x56
// out: (32, 256, 60, 60) fp32 = 112 MB -> 8192 planes of 60x60
//
// R4 structure (2 aligned LDG.64 per output float4, ILP=4, regs ~30,
// occ ~81%) + cache-policy steering:
//   - input loads:  ld.global.nc.L2::cache_hint with a
//                   createpolicy.fractional.L2::evict_last policy
//                   (inline evict_last modifier is illegal on .v2 loads)
//   - output stores: st.global.cs (streaming/evict-first)
// Goal: cut DRAM traffic from ~163MB (measured R4) toward ~120-140MB.

#define IN_H   56
#define IN_W   56
#define PAD    2
#define PLANE_IN      (IN_H * IN_W)          // 3136
#define VEC_PER_ROW   15                     // 60/4
#define VEC_PER_PLANE (60 * VEC_PER_ROW)     // 900
#define ILP 4
#define THREADS 256
#define CHUNK (THREADS * ILP)                // 1024

__device__ __forceinline__ unsigned long long mk_evict_last_policy() {
    unsigned long long pol;
    asm("createpolicy.fractional.L2::evict_last.b64 %0, 1.0;" : "=l"(pol));
    return pol;
}

__device__ __forceinline__ float2 ldg_keep(const float* p, unsigned long long pol) {
    float2 v;
    asm("ld.global.nc.L2::cache_hint.v2.f32 {%0,%1}, [%2], %3;"
        : "=f"(v.x), "=f"(v.y) : "l"(p), "l"(pol));
    return v;
}

__device__ __forceinline__ void stg_stream(float4* p, float4 v) {
    asm volatile("st.global.cs.v4.f32 [%0], {%1,%2,%3,%4};"
                 :: "l"(p), "f"(v.x), "f"(v.y), "f"(v.z), "f"(v.w)
                 : "memory");
}

__global__ __launch_bounds__(THREADS)
void pad2d_edge_cpol(const float* __restrict__ x,
                     float4* __restrict__ out)
{
    const int base = blockIdx.x * CHUNK + threadIdx.x;
    const unsigned long long pol = mk_evict_last_policy();

    float2 a[ILP], b[ILP];
    int    w0[ILP];

#pragma unroll
    for (int k = 0; k < ILP; k++) {
        int idx   = base + k * THREADS;
        int plane = idx / VEC_PER_PLANE;
        int rem   = idx - plane * VEC_PER_PLANE;
        int h     = rem / VEC_PER_ROW;
        int w     = (rem - h * VEC_PER_ROW) * 4;
        w0[k]     = w;
        int hin   = min(max(h - PAD, 0), IN_H - 1);
        int off   = plane * PLANE_IN + hin * IN_W;   // max ~25.7M, fits 32-bit

        // both addresses 8-byte aligned
        a[k] = ldg_keep(x + off + max(w - 2, 0), pol);
        b[k] = ldg_keep(x + off + min(w, IN_W - 2), pol);
    }

#pragma unroll
    for (int k = 0; k < ILP; k++) {
        int w = w0[k];
        float4 v;
        v.x = a[k].x;
        v.y = (w == 0)    ? a[k].x : a[k].y;   // left edge replicates col 0
        v.z = (w == IN_W) ? b[k].y : b[k].x;   // right edge replicates col 55
        v.w = b[k].y;
        stg_stream(out + base + k * THREADS, v);
    }
}

extern "C" void kernel_launch(void* const* d_in, const int* in_sizes, int n_in,
                              void* d_out, int out_size)
{
    const float* x = (const float*)d_in[0];
    float4* out = (float4*)d_out;

    int nvec = out_size / 4;        // 7,372,800
    int blocks = nvec / CHUNK;      // 7200 exactly
    pad2d_edge_cpol<<<blocks, THREADS>>>(x, out);
}